// round 1
// baseline (speedup 1.0000x reference)
#include <cuda_runtime.h>

#define BB 8
#define NN 1024
#define DD 128

// ---------------- scratch (device globals; no allocation allowed) ----------
__device__ float g_v[BB * NN * DD];
__device__ float g_k[BB * NN * DD];
__device__ float g_q[BB * NN * DD];
__device__ float g_kpe[NN * NN];
__device__ float g_vpe[NN * DD];

// ---------------- kpe[n,m] = sum_d keys_pos_enc[n,m,d] ---------------------
// one warp per (n,m): 32 lanes x float4 = 128 contiguous floats
__global__ void kpe_kernel(const float* __restrict__ kp) {
    int w = blockIdx.x * 8 + (threadIdx.x >> 5);
    int lane = threadIdx.x & 31;
    const float4* p = reinterpret_cast<const float4*>(kp) + (size_t)w * 32;
    float4 v = p[lane];
    float s = v.x + v.y + v.z + v.w;
#pragma unroll
    for (int o = 16; o >= 1; o >>= 1)
        s += __shfl_xor_sync(0xffffffffu, s, o);
    if (lane == 0) g_kpe[w] = s;
}

// ---------------- vpe[n,d] = sum_m values_pos_enc[n,m,d] -------------------
__global__ void vpe_kernel(const float* __restrict__ vp) {
    __shared__ float4 red[8][32];
    int n = blockIdx.x;
    int g = threadIdx.x >> 5, lane = threadIdx.x & 31;
    const float4* base = reinterpret_cast<const float4*>(vp + (size_t)n * NN * DD);
    float4 acc = make_float4(0.f, 0.f, 0.f, 0.f);
#pragma unroll 4
    for (int m = g; m < NN; m += 8) {
        float4 v = base[m * 32 + lane];
        acc.x += v.x; acc.y += v.y; acc.z += v.z; acc.w += v.w;
    }
    red[g][lane] = acc;
    __syncthreads();
    if (g == 0) {
        float4 a = red[0][lane];
#pragma unroll
        for (int i = 1; i < 8; i++) {
            float4 b = red[i][lane];
            a.x += b.x; a.y += b.y; a.z += b.z; a.w += b.w;
        }
        reinterpret_cast<float4*>(g_vpe + n * DD)[lane] = a;
    }
}

// ---------------- projection: Y[r,o] = sum_e X[r,e] * W[o,e] ---------------
// block: 64 rows x 128 outs, 256 threads, each 4x8 register tile
#define PROJ_SMEM ((64 * 132 + 128 * 132) * 4)
__global__ void proj_kernel(const float* __restrict__ Xin,
                            const float* __restrict__ W, int dst) {
    extern __shared__ float sm[];
    float* sX = sm;               // 64 x 132
    float* sWt = sm + 64 * 132;   // transposed: sWt[e*132 + o]
    const float* X = Xin ? Xin : g_v;
    float* Y = (dst == 0) ? g_v : (dst == 1 ? g_k : g_q);

    int tid = threadIdx.x;
    int row0 = blockIdx.x * 64;
    for (int it = tid; it < 64 * 32; it += 256) {
        int r = it >> 5, c4 = it & 31;
        float4 v = *reinterpret_cast<const float4*>(X + (size_t)(row0 + r) * DD + c4 * 4);
        *reinterpret_cast<float4*>(sX + r * 132 + c4 * 4) = v;
    }
    for (int it = tid; it < 128 * 32; it += 256) {
        int o = it >> 5, e4 = it & 31;
        float4 v = *reinterpret_cast<const float4*>(W + o * DD + e4 * 4);
        sWt[(e4 * 4 + 0) * 132 + o] = v.x;
        sWt[(e4 * 4 + 1) * 132 + o] = v.y;
        sWt[(e4 * 4 + 2) * 132 + o] = v.z;
        sWt[(e4 * 4 + 3) * 132 + o] = v.w;
    }
    __syncthreads();

    int ty = tid >> 4, tx = tid & 15;
    float acc[4][8];
#pragma unroll
    for (int i = 0; i < 4; i++)
#pragma unroll
        for (int j = 0; j < 8; j++) acc[i][j] = 0.f;

    for (int kk = 0; kk < 128; kk += 4) {
        float4 a[4];
#pragma unroll
        for (int i = 0; i < 4; i++)
            a[i] = *reinterpret_cast<const float4*>(sX + (ty * 4 + i) * 132 + kk);
#pragma unroll
        for (int t = 0; t < 4; t++) {
            float4 b0 = *reinterpret_cast<const float4*>(sWt + (kk + t) * 132 + tx * 8);
            float4 b1 = *reinterpret_cast<const float4*>(sWt + (kk + t) * 132 + tx * 8 + 4);
#pragma unroll
            for (int i = 0; i < 4; i++) {
                float aa = reinterpret_cast<const float*>(&a[i])[t];
                acc[i][0] += aa * b0.x; acc[i][1] += aa * b0.y;
                acc[i][2] += aa * b0.z; acc[i][3] += aa * b0.w;
                acc[i][4] += aa * b1.x; acc[i][5] += aa * b1.y;
                acc[i][6] += aa * b1.z; acc[i][7] += aa * b1.w;
            }
        }
    }
#pragma unroll
    for (int i = 0; i < 4; i++) {
        float* yp = Y + (size_t)(row0 + ty * 4 + i) * DD + tx * 8;
        *reinterpret_cast<float4*>(yp) = make_float4(acc[i][0], acc[i][1], acc[i][2], acc[i][3]);
        *reinterpret_cast<float4*>(yp + 4) = make_float4(acc[i][4], acc[i][5], acc[i][6], acc[i][7]);
    }
}

// ---------------- fused attention + epilogue -------------------------------
// block = (row tile of 64, batch). 256 threads. Flash-style online softmax.
#define ATTN_SMEM ((64 * 132 + 64 * 128 + 64 * 128 + 64 * 68 + 64 + 64) * 4)
__global__ void attn_kernel(const int* __restrict__ mask,
                            const float* __restrict__ gamma,
                            const float* __restrict__ beta,
                            float* __restrict__ out) {
    extern __shared__ float sm[];
    float* sQ = sm;                     // 64 x 132 (row-major, padded)
    float* sK = sQ + 64 * 132;          // 64 x 128 (16B-unit XOR swizzled)
    float* sV = sK + 64 * 128;          // 64 x 128 (row-major)
    float* sP = sV + 64 * 128;          // 64 x 68
    float* sScale = sP + 64 * 68;       // 64
    float* sL = sScale + 64;            // 64

    int tid = threadIdx.x;
    int b = blockIdx.y;
    int n0 = blockIdx.x * 64;
    const float inv_s = 0.088388347648318447f;  // 1/sqrt(128)

    // load Q tile pre-scaled by 1/sqrt(D)
    for (int it = tid; it < 64 * 32; it += 256) {
        int r = it >> 5, c4 = it & 31;
        float4 v = *reinterpret_cast<const float4*>(
            g_q + ((size_t)(b * NN + n0 + r)) * DD + c4 * 4);
        v.x *= inv_s; v.y *= inv_s; v.z *= inv_s; v.w *= inv_s;
        *reinterpret_cast<float4*>(sQ + r * 132 + c4 * 4) = v;
    }

    int ty = tid >> 4, tx = tid & 15;   // S-GEMM: rows ty*4+i, cols tx+16j
    int oy = tid >> 5, ox = tid & 31;   // O-GEMM: rows oy*8+i, cols ox*4+j

    float m_run[4], l_run[4];
    float acc_o[8][4];
#pragma unroll
    for (int i = 0; i < 4; i++) { m_run[i] = -1e30f; l_run[i] = 0.f; }
#pragma unroll
    for (int i = 0; i < 8; i++)
#pragma unroll
        for (int j = 0; j < 4; j++) acc_o[i][j] = 0.f;

    for (int t = 0; t < 16; t++) {
        int m0 = t * 64;
        __syncthreads();  // previous iter's reads of sK/sV/sP done
        for (int it = tid; it < 64 * 32; it += 256) {
            int r = it >> 5, c4 = it & 31;
            size_t gro = ((size_t)(b * NN + m0 + r)) * DD + c4 * 4;
            float4 kv = *reinterpret_cast<const float4*>(g_k + gro);
            *reinterpret_cast<float4*>(sK + r * 128 + ((c4 ^ (r & 7)) * 4)) = kv;
            float4 vv = *reinterpret_cast<const float4*>(g_v + gro);
            *reinterpret_cast<float4*>(sV + r * 128 + c4 * 4) = vv;
        }
        __syncthreads();

        // S = Q K^T  (scaled, since Q pre-scaled)
        float s[4][4];
#pragma unroll
        for (int i = 0; i < 4; i++)
#pragma unroll
            for (int j = 0; j < 4; j++) s[i][j] = 0.f;

        for (int kk = 0; kk < 128; kk += 4) {
            int kkv = kk >> 2;
            float4 a[4];
#pragma unroll
            for (int i = 0; i < 4; i++)
                a[i] = *reinterpret_cast<const float4*>(sQ + (ty * 4 + i) * 132 + kk);
#pragma unroll
            for (int j = 0; j < 4; j++) {
                int col = tx + j * 16;
                float4 bv = *reinterpret_cast<const float4*>(
                    sK + col * 128 + ((kkv ^ (col & 7)) * 4));
#pragma unroll
                for (int i = 0; i < 4; i++)
                    s[i][j] += a[i].x * bv.x + a[i].y * bv.y +
                               a[i].z * bv.z + a[i].w * bv.w;
            }
        }

        // + kpe/sqrt(D), mask, online softmax
#pragma unroll
        for (int i = 0; i < 4; i++) {
            int n = n0 + ty * 4 + i;
            const float* kpe_row = g_kpe + (size_t)n * NN + m0;
            const int* mrow = mask + ((size_t)b * NN + n) * NN + m0;
            float mx = -1e30f;
#pragma unroll
            for (int j = 0; j < 4; j++) {
                int c = tx + j * 16;
                float e = s[i][j] + kpe_row[c] * inv_s;
                e = (mrow[c] != 0) ? e : -1e30f;
                s[i][j] = e;
                mx = fmaxf(mx, e);
            }
#pragma unroll
            for (int o = 8; o >= 1; o >>= 1)
                mx = fmaxf(mx, __shfl_xor_sync(0xffffffffu, mx, o));
            float mn = fmaxf(m_run[i], mx);
            float f = __expf(m_run[i] - mn);
            float rs = 0.f;
#pragma unroll
            for (int j = 0; j < 4; j++) {
                float p = (s[i][j] < -5e29f) ? 0.f : __expf(s[i][j] - mn);
                sP[(ty * 4 + i) * 68 + tx + j * 16] = p;
                rs += p;
            }
#pragma unroll
            for (int o = 8; o >= 1; o >>= 1)
                rs += __shfl_xor_sync(0xffffffffu, rs, o);
            l_run[i] = l_run[i] * f + rs;
            m_run[i] = mn;
            if (tx == 0) sScale[ty * 4 + i] = f;
        }
        __syncthreads();

        // O = diag(f) O + P V
#pragma unroll
        for (int i = 0; i < 8; i++) {
            float f = sScale[oy * 8 + i];
#pragma unroll
            for (int j = 0; j < 4; j++) acc_o[i][j] *= f;
        }
        for (int m = 0; m < 64; m += 4) {
            float4 a4[8];
#pragma unroll
            for (int i = 0; i < 8; i++)
                a4[i] = *reinterpret_cast<const float4*>(sP + (oy * 8 + i) * 68 + m);
#pragma unroll
            for (int mt = 0; mt < 4; mt++) {
                float4 bv = *reinterpret_cast<const float4*>(sV + (m + mt) * 128 + ox * 4);
#pragma unroll
                for (int i = 0; i < 8; i++) {
                    float p = reinterpret_cast<const float*>(&a4[i])[mt];
                    acc_o[i][0] += p * bv.x; acc_o[i][1] += p * bv.y;
                    acc_o[i][2] += p * bv.z; acc_o[i][3] += p * bv.w;
                }
            }
        }
    }

    if (tx == 0) {
#pragma unroll
        for (int i = 0; i < 4; i++) sL[ty * 4 + i] = l_run[i];
    }
    __syncthreads();

    // pre-LN rows: O/l + vpe  -> sO (alias of sK; sK dead past here)
    float* sO = sK;
#pragma unroll
    for (int i = 0; i < 8; i++) {
        int r = oy * 8 + i;
        int n = n0 + r;
        float il = 1.0f / sL[r];
        const float* vper = g_vpe + n * DD + ox * 4;
        float4 ov;
        ov.x = acc_o[i][0] * il + vper[0];
        ov.y = acc_o[i][1] * il + vper[1];
        ov.z = acc_o[i][2] * il + vper[2];
        ov.w = acc_o[i][3] * il + vper[3];
        *reinterpret_cast<float4*>(sO + r * 128 + ox * 4) = ov;
    }
    __syncthreads();

    // LayerNorm + residual: 4 threads per row
    int row = tid >> 2, part = tid & 3;
    float sum = 0.f, sq = 0.f;
#pragma unroll
    for (int u = 0; u < 32; u += 4) {
        float4 x = *reinterpret_cast<const float4*>(sO + row * 128 + part * 32 + u);
        sum += x.x + x.y + x.z + x.w;
        sq += x.x * x.x + x.y * x.y + x.z * x.z + x.w * x.w;
    }
#pragma unroll
    for (int o = 1; o <= 2; o <<= 1) {
        sum += __shfl_xor_sync(0xffffffffu, sum, o);
        sq += __shfl_xor_sync(0xffffffffu, sq, o);
    }
    float mu = sum * (1.f / 128.f);
    float var = sq * (1.f / 128.f) - mu * mu;
    float rstd = rsqrtf(var + 1e-5f);
    int n = n0 + row;
    const float* gvr = g_v + ((size_t)(b * NN + n)) * DD;
    float* orow = out + ((size_t)(b * NN + n)) * DD;
#pragma unroll
    for (int u = 0; u < 32; u += 4) {
        int d = part * 32 + u;
        float4 x = *reinterpret_cast<const float4*>(sO + row * 128 + d);
        float4 gm = *reinterpret_cast<const float4*>(gamma + d);
        float4 bt = *reinterpret_cast<const float4*>(beta + d);
        float4 vv = *reinterpret_cast<const float4*>(gvr + d);
        float4 r4;
        r4.x = (x.x - mu) * rstd * gm.x + bt.x + vv.x;
        r4.y = (x.y - mu) * rstd * gm.y + bt.y + vv.y;
        r4.z = (x.z - mu) * rstd * gm.z + bt.z + vv.z;
        r4.w = (x.w - mu) * rstd * gm.w + bt.w + vv.w;
        *reinterpret_cast<float4*>(orow + d) = r4;
    }
}

// ---------------- launch ---------------------------------------------------
extern "C" void kernel_launch(void* const* d_in, const int* in_sizes, int n_in,
                              void* d_out, int out_size) {
    const float* values = (const float*)d_in[0];
    // d_in[1] keys, d_in[2] queries: unused (faithful to reference)
    const int* mask = (const int*)d_in[3];
    const float* vpe = (const float*)d_in[4];
    const float* kpe = (const float*)d_in[5];
    const float* Wv = (const float*)d_in[6];
    const float* Wk = (const float*)d_in[7];
    const float* Wq = (const float*)d_in[8];
    const float* ln_gamma = (const float*)d_in[9];
    const float* ln_beta = (const float*)d_in[10];
    float* out = (float*)d_out;

    cudaFuncSetAttribute(proj_kernel, cudaFuncAttributeMaxDynamicSharedMemorySize, PROJ_SMEM);
    cudaFuncSetAttribute(attn_kernel, cudaFuncAttributeMaxDynamicSharedMemorySize, ATTN_SMEM);

    kpe_kernel<<<NN * NN / 8, 256>>>(kpe);
    vpe_kernel<<<NN, 256>>>(vpe);
    proj_kernel<<<BB * NN / 64, 256, PROJ_SMEM>>>(values, Wv, 0);  // v
    proj_kernel<<<BB * NN / 64, 256, PROJ_SMEM>>>(nullptr, Wk, 1); // k = v Wk^T
    proj_kernel<<<BB * NN / 64, 256, PROJ_SMEM>>>(nullptr, Wq, 2); // q = v Wq^T
    attn_kernel<<<dim3(NN / 64, BB), 256, ATTN_SMEM>>>(mask, ln_gamma, ln_beta, out);
}

// round 2
// speedup vs baseline: 1.0506x; 1.0506x over previous
#include <cuda_runtime.h>

#define BB 8
#define NN 1024
#define DD 128

// ---------------- scratch (device globals; no allocation allowed) ----------
__device__ float g_v[BB * NN * DD];
__device__ float g_k[BB * NN * DD];
__device__ float g_q[BB * NN * DD];
__device__ float g_kpe[NN * NN];
__device__ float g_vpe[NN * DD];

// ---------------- kpe[n,m] = sum_d keys_pos_enc[n,m,d] ---------------------
// one warp per (n,m): 32 lanes x float4 = 128 contiguous floats
__global__ void kpe_kernel(const float* __restrict__ kp) {
    int w = blockIdx.x * 8 + (threadIdx.x >> 5);
    int lane = threadIdx.x & 31;
    const float4* p = reinterpret_cast<const float4*>(kp) + (size_t)w * 32;
    float4 v = p[lane];
    float s = v.x + v.y + v.z + v.w;
#pragma unroll
    for (int o = 16; o >= 1; o >>= 1)
        s += __shfl_xor_sync(0xffffffffu, s, o);
    if (lane == 0) g_kpe[w] = s;
}

// ---------------- vpe[n,d] = sum_m values_pos_enc[n,m,d] -------------------
__global__ void vpe_kernel(const float* __restrict__ vp) {
    __shared__ float4 red[8][32];
    int n = blockIdx.x;
    int g = threadIdx.x >> 5, lane = threadIdx.x & 31;
    const float4* base = reinterpret_cast<const float4*>(vp + (size_t)n * NN * DD);
    float4 acc = make_float4(0.f, 0.f, 0.f, 0.f);
#pragma unroll 4
    for (int m = g; m < NN; m += 8) {
        float4 v = base[m * 32 + lane];
        acc.x += v.x; acc.y += v.y; acc.z += v.z; acc.w += v.w;
    }
    red[g][lane] = acc;
    __syncthreads();
    if (g == 0) {
        float4 a = red[0][lane];
#pragma unroll
        for (int i = 1; i < 8; i++) {
            float4 b = red[i][lane];
            a.x += b.x; a.y += b.y; a.z += b.z; a.w += b.w;
        }
        reinterpret_cast<float4*>(g_vpe + n * DD)[lane] = a;
    }
}

// ---------------- fused projection: v = X Wv^T; k = v Wk^T; q = v Wq^T -----
// block: 64 rows, 256 threads, each 4x8 register tile. v kept in smem for k,q.
#define FPROJ_SMEM ((64 * 132 + 64 * 132 + 128 * 132) * 4)

// GEMM core: acc[4][8] += A(64x128, stride 132) * Wt(128x128, stride 132)
__device__ __forceinline__ void gemm_64x128(const float* __restrict__ sA,
                                            const float* __restrict__ sWt,
                                            int ty, int tx, float acc[4][8]) {
#pragma unroll
    for (int i = 0; i < 4; i++)
#pragma unroll
        for (int j = 0; j < 8; j++) acc[i][j] = 0.f;
    for (int kk = 0; kk < 128; kk += 4) {
        float4 a[4];
#pragma unroll
        for (int i = 0; i < 4; i++)
            a[i] = *reinterpret_cast<const float4*>(sA + (ty * 4 + i) * 132 + kk);
#pragma unroll
        for (int t = 0; t < 4; t++) {
            float4 b0 = *reinterpret_cast<const float4*>(sWt + (kk + t) * 132 + tx * 8);
            float4 b1 = *reinterpret_cast<const float4*>(sWt + (kk + t) * 132 + tx * 8 + 4);
#pragma unroll
            for (int i = 0; i < 4; i++) {
                float aa = reinterpret_cast<const float*>(&a[i])[t];
                acc[i][0] += aa * b0.x; acc[i][1] += aa * b0.y;
                acc[i][2] += aa * b0.z; acc[i][3] += aa * b0.w;
                acc[i][4] += aa * b1.x; acc[i][5] += aa * b1.y;
                acc[i][6] += aa * b1.z; acc[i][7] += aa * b1.w;
            }
        }
    }
}

__device__ __forceinline__ void load_wt(const float* __restrict__ W,
                                        float* __restrict__ sWt, int tid) {
    for (int it = tid; it < 128 * 32; it += 256) {
        int o = it >> 5, e4 = it & 31;
        float4 v = *reinterpret_cast<const float4*>(W + o * DD + e4 * 4);
        sWt[(e4 * 4 + 0) * 132 + o] = v.x;
        sWt[(e4 * 4 + 1) * 132 + o] = v.y;
        sWt[(e4 * 4 + 2) * 132 + o] = v.z;
        sWt[(e4 * 4 + 3) * 132 + o] = v.w;
    }
}

__global__ __launch_bounds__(256) void proj_fused_kernel(
    const float* __restrict__ X, const float* __restrict__ Wv,
    const float* __restrict__ Wk, const float* __restrict__ Wq) {
    extern __shared__ float sm[];
    float* sX = sm;                     // 64 x 132
    float* sV = sm + 64 * 132;          // 64 x 132
    float* sWt = sm + 2 * 64 * 132;     // 128 x 132 (transposed weight)

    int tid = threadIdx.x;
    int row0 = blockIdx.x * 64;
    int ty = tid >> 4, tx = tid & 15;
    float acc[4][8];

    // load X tile + Wv
    for (int it = tid; it < 64 * 32; it += 256) {
        int r = it >> 5, c4 = it & 31;
        float4 v = *reinterpret_cast<const float4*>(X + (size_t)(row0 + r) * DD + c4 * 4);
        *reinterpret_cast<float4*>(sX + r * 132 + c4 * 4) = v;
    }
    load_wt(Wv, sWt, tid);
    __syncthreads();

    // v = X Wv^T
    gemm_64x128(sX, sWt, ty, tx, acc);
    __syncthreads();  // all reads of sWt done before overwrite
#pragma unroll
    for (int i = 0; i < 4; i++) {
        int r = ty * 4 + i;
        float4 lo = make_float4(acc[i][0], acc[i][1], acc[i][2], acc[i][3]);
        float4 hi = make_float4(acc[i][4], acc[i][5], acc[i][6], acc[i][7]);
        *reinterpret_cast<float4*>(sV + r * 132 + tx * 8) = lo;
        *reinterpret_cast<float4*>(sV + r * 132 + tx * 8 + 4) = hi;
        float* gp = g_v + (size_t)(row0 + r) * DD + tx * 8;
        *reinterpret_cast<float4*>(gp) = lo;
        *reinterpret_cast<float4*>(gp + 4) = hi;
    }
    load_wt(Wk, sWt, tid);
    __syncthreads();

    // k = v Wk^T
    gemm_64x128(sV, sWt, ty, tx, acc);
#pragma unroll
    for (int i = 0; i < 4; i++) {
        float* gp = g_k + (size_t)(row0 + ty * 4 + i) * DD + tx * 8;
        *reinterpret_cast<float4*>(gp) = make_float4(acc[i][0], acc[i][1], acc[i][2], acc[i][3]);
        *reinterpret_cast<float4*>(gp + 4) = make_float4(acc[i][4], acc[i][5], acc[i][6], acc[i][7]);
    }
    __syncthreads();  // reads of sWt done
    load_wt(Wq, sWt, tid);
    __syncthreads();

    // q = v Wq^T
    gemm_64x128(sV, sWt, ty, tx, acc);
#pragma unroll
    for (int i = 0; i < 4; i++) {
        float* gp = g_q + (size_t)(row0 + ty * 4 + i) * DD + tx * 8;
        *reinterpret_cast<float4*>(gp) = make_float4(acc[i][0], acc[i][1], acc[i][2], acc[i][3]);
        *reinterpret_cast<float4*>(gp + 4) = make_float4(acc[i][4], acc[i][5], acc[i][6], acc[i][7]);
    }
}

// ---------------- fused attention + epilogue -------------------------------
// block = (row tile of 64, batch). 256 threads. Flash-style online softmax.
#define ATTN_SMEM ((64 * 132 + 64 * 128 + 64 * 128 + 64 * 68 + 64 + 64) * 4)
__global__ __launch_bounds__(256) void attn_kernel(
    const int* __restrict__ mask, const float* __restrict__ gamma,
    const float* __restrict__ beta, float* __restrict__ out) {
    extern __shared__ float sm[];
    float* sQ = sm;                     // 64 x 132 (row-major, padded)
    float* sK = sQ + 64 * 132;          // 64 x 128 (16B-unit XOR swizzled)
    float* sV = sK + 64 * 128;          // 64 x 128 (row-major)
    float* sP = sV + 64 * 128;          // 64 x 68
    float* sScale = sP + 64 * 68;       // 64
    float* sL = sScale + 64;            // 64

    int tid = threadIdx.x;
    int b = blockIdx.y;
    int n0 = blockIdx.x * 64;
    const float inv_s = 0.088388347648318447f;  // 1/sqrt(128)

    // load Q tile pre-scaled by 1/sqrt(D)
    for (int it = tid; it < 64 * 32; it += 256) {
        int r = it >> 5, c4 = it & 31;
        float4 v = *reinterpret_cast<const float4*>(
            g_q + ((size_t)(b * NN + n0 + r)) * DD + c4 * 4);
        v.x *= inv_s; v.y *= inv_s; v.z *= inv_s; v.w *= inv_s;
        *reinterpret_cast<float4*>(sQ + r * 132 + c4 * 4) = v;
    }

    int ty = tid >> 4, tx = tid & 15;   // S-GEMM: rows ty*4+i, cols tx+16j
    int oy = tid >> 5, ox = tid & 31;   // O-GEMM: rows oy*8+i, cols ox*4+j

    float m_run[4], l_run[4];
    float acc_o[8][4];
#pragma unroll
    for (int i = 0; i < 4; i++) { m_run[i] = -1e30f; l_run[i] = 0.f; }
#pragma unroll
    for (int i = 0; i < 8; i++)
#pragma unroll
        for (int j = 0; j < 4; j++) acc_o[i][j] = 0.f;

    for (int t = 0; t < 16; t++) {
        int m0 = t * 64;
        __syncthreads();  // previous iter's reads of sK/sV/sP done
        for (int it = tid; it < 64 * 32; it += 256) {
            int r = it >> 5, c4 = it & 31;
            size_t gro = ((size_t)(b * NN + m0 + r)) * DD + c4 * 4;
            float4 kv = *reinterpret_cast<const float4*>(g_k + gro);
            *reinterpret_cast<float4*>(sK + r * 128 + ((c4 ^ (r & 7)) * 4)) = kv;
            float4 vv = *reinterpret_cast<const float4*>(g_v + gro);
            *reinterpret_cast<float4*>(sV + r * 128 + c4 * 4) = vv;
        }
        __syncthreads();

        // S = Q K^T  (scaled, since Q pre-scaled)
        float s[4][4];
#pragma unroll
        for (int i = 0; i < 4; i++)
#pragma unroll
            for (int j = 0; j < 4; j++) s[i][j] = 0.f;

        for (int kk = 0; kk < 128; kk += 4) {
            int kkv = kk >> 2;
            float4 a[4];
#pragma unroll
            for (int i = 0; i < 4; i++)
                a[i] = *reinterpret_cast<const float4*>(sQ + (ty * 4 + i) * 132 + kk);
#pragma unroll
            for (int j = 0; j < 4; j++) {
                int col = tx + j * 16;
                float4 bv = *reinterpret_cast<const float4*>(
                    sK + col * 128 + ((kkv ^ (col & 7)) * 4));
#pragma unroll
                for (int i = 0; i < 4; i++)
                    s[i][j] += a[i].x * bv.x + a[i].y * bv.y +
                               a[i].z * bv.z + a[i].w * bv.w;
            }
        }

        // + kpe/sqrt(D), mask, online softmax
#pragma unroll
        for (int i = 0; i < 4; i++) {
            int n = n0 + ty * 4 + i;
            const float* kpe_row = g_kpe + (size_t)n * NN + m0;
            const int* mrow = mask + ((size_t)b * NN + n) * NN + m0;
            float mx = -1e30f;
#pragma unroll
            for (int j = 0; j < 4; j++) {
                int c = tx + j * 16;
                float e = s[i][j] + kpe_row[c] * inv_s;
                e = (mrow[c] != 0) ? e : -1e30f;
                s[i][j] = e;
                mx = fmaxf(mx, e);
            }
#pragma unroll
            for (int o = 8; o >= 1; o >>= 1)
                mx = fmaxf(mx, __shfl_xor_sync(0xffffffffu, mx, o));
            float mn = fmaxf(m_run[i], mx);
            float f = __expf(m_run[i] - mn);
            float rs = 0.f;
#pragma unroll
            for (int j = 0; j < 4; j++) {
                float p = (s[i][j] < -5e29f) ? 0.f : __expf(s[i][j] - mn);
                sP[(ty * 4 + i) * 68 + tx + j * 16] = p;
                rs += p;
            }
#pragma unroll
            for (int o = 8; o >= 1; o >>= 1)
                rs += __shfl_xor_sync(0xffffffffu, rs, o);
            l_run[i] = l_run[i] * f + rs;
            m_run[i] = mn;
            if (tx == 0) sScale[ty * 4 + i] = f;
        }
        __syncthreads();

        // O = diag(f) O + P V
#pragma unroll
        for (int i = 0; i < 8; i++) {
            float f = sScale[oy * 8 + i];
#pragma unroll
            for (int j = 0; j < 4; j++) acc_o[i][j] *= f;
        }
        for (int m = 0; m < 64; m += 4) {
            float4 a4[8];
#pragma unroll
            for (int i = 0; i < 8; i++)
                a4[i] = *reinterpret_cast<const float4*>(sP + (oy * 8 + i) * 68 + m);
#pragma unroll
            for (int mt = 0; mt < 4; mt++) {
                float4 bv = *reinterpret_cast<const float4*>(sV + (m + mt) * 128 + ox * 4);
#pragma unroll
                for (int i = 0; i < 8; i++) {
                    float p = reinterpret_cast<const float*>(&a4[i])[mt];
                    acc_o[i][0] += p * bv.x; acc_o[i][1] += p * bv.y;
                    acc_o[i][2] += p * bv.z; acc_o[i][3] += p * bv.w;
                }
            }
        }
    }

    if (tx == 0) {
#pragma unroll
        for (int i = 0; i < 4; i++) sL[ty * 4 + i] = l_run[i];
    }
    __syncthreads();

    // pre-LN rows: O/l + vpe  -> sO (alias of sK; sK dead past here)
    float* sO = sK;
#pragma unroll
    for (int i = 0; i < 8; i++) {
        int r = oy * 8 + i;
        int n = n0 + r;
        float il = 1.0f / sL[r];
        const float* vper = g_vpe + n * DD + ox * 4;
        float4 ov;
        ov.x = acc_o[i][0] * il + vper[0];
        ov.y = acc_o[i][1] * il + vper[1];
        ov.z = acc_o[i][2] * il + vper[2];
        ov.w = acc_o[i][3] * il + vper[3];
        *reinterpret_cast<float4*>(sO + r * 128 + ox * 4) = ov;
    }
    __syncthreads();

    // LayerNorm + residual: 4 threads per row
    int row = tid >> 2, part = tid & 3;
    float sum = 0.f, sq = 0.f;
#pragma unroll
    for (int u = 0; u < 32; u += 4) {
        float4 x = *reinterpret_cast<const float4*>(sO + row * 128 + part * 32 + u);
        sum += x.x + x.y + x.z + x.w;
        sq += x.x * x.x + x.y * x.y + x.z * x.z + x.w * x.w;
    }
#pragma unroll
    for (int o = 1; o <= 2; o <<= 1) {
        sum += __shfl_xor_sync(0xffffffffu, sum, o);
        sq += __shfl_xor_sync(0xffffffffu, sq, o);
    }
    float mu = sum * (1.f / 128.f);
    float var = sq * (1.f / 128.f) - mu * mu;
    float rstd = rsqrtf(var + 1e-5f);
    int n = n0 + row;
    const float* gvr = g_v + ((size_t)(b * NN + n)) * DD;
    float* orow = out + ((size_t)(b * NN + n)) * DD;
#pragma unroll
    for (int u = 0; u < 32; u += 4) {
        int d = part * 32 + u;
        float4 x = *reinterpret_cast<const float4*>(sO + row * 128 + d);
        float4 gm = *reinterpret_cast<const float4*>(gamma + d);
        float4 bt = *reinterpret_cast<const float4*>(beta + d);
        float4 vv = *reinterpret_cast<const float4*>(gvr + d);
        float4 r4;
        r4.x = (x.x - mu) * rstd * gm.x + bt.x + vv.x;
        r4.y = (x.y - mu) * rstd * gm.y + bt.y + vv.y;
        r4.z = (x.z - mu) * rstd * gm.z + bt.z + vv.z;
        r4.w = (x.w - mu) * rstd * gm.w + bt.w + vv.w;
        *reinterpret_cast<float4*>(orow + d) = r4;
    }
}

// ---------------- launch ---------------------------------------------------
extern "C" void kernel_launch(void* const* d_in, const int* in_sizes, int n_in,
                              void* d_out, int out_size) {
    const float* values = (const float*)d_in[0];
    // d_in[1] keys, d_in[2] queries: unused (faithful to reference)
    const int* mask = (const int*)d_in[3];
    const float* vpe = (const float*)d_in[4];
    const float* kpe = (const float*)d_in[5];
    const float* Wv = (const float*)d_in[6];
    const float* Wk = (const float*)d_in[7];
    const float* Wq = (const float*)d_in[8];
    const float* ln_gamma = (const float*)d_in[9];
    const float* ln_beta = (const float*)d_in[10];
    float* out = (float*)d_out;

    static cudaStream_t s2 = nullptr;
    static cudaEvent_t ev_fork = nullptr, ev_join = nullptr;
    if (!s2) {
        cudaStreamCreateWithFlags(&s2, cudaStreamNonBlocking);
        cudaEventCreateWithFlags(&ev_fork, cudaEventDisableTiming);
        cudaEventCreateWithFlags(&ev_join, cudaEventDisableTiming);
        cudaFuncSetAttribute(proj_fused_kernel,
                             cudaFuncAttributeMaxDynamicSharedMemorySize, FPROJ_SMEM);
        cudaFuncSetAttribute(attn_kernel,
                             cudaFuncAttributeMaxDynamicSharedMemorySize, ATTN_SMEM);
    }

    // fork: pos-enc reductions (HBM-bound) on s2, projections (compute) on s0
    cudaEventRecord(ev_fork, 0);
    cudaStreamWaitEvent(s2, ev_fork, 0);
    kpe_kernel<<<NN * NN / 8, 256, 0, s2>>>(kpe);
    vpe_kernel<<<NN, 256, 0, s2>>>(vpe);
    proj_fused_kernel<<<BB * NN / 64, 256, FPROJ_SMEM>>>(values, Wv, Wk, Wq);
    // join, then attention
    cudaEventRecord(ev_join, s2);
    cudaStreamWaitEvent(0, ev_join, 0);
    attn_kernel<<<dim3(NN / 64, BB), 256, ATTN_SMEM>>>(mask, ln_gamma, ln_beta, out);
}